// round 5
// baseline (speedup 1.0000x reference)
#include <cuda_runtime.h>

#define BATCH 4
#define NPTS  8192
#define SPTS  2048
#define D1C   128
#define D2C   256
#define CIN   384
#define HCH   256
#define BN_TOT (BATCH * NPTS)   // 32768
#define NTILES 512              // (BATCH*NPTS)/64 column tiles

// ---------------- scratch (static device globals; no allocation allowed) ----
__device__ int   g_idx[BATCH * NPTS * 3];
__device__ float g_w[BATCH * NPTS * 3];
__device__ float g_interp[BATCH * D2C * NPTS];   // 32 MB
__device__ float g_y1[BATCH * HCH * NPTS];       // 32 MB
__device__ float g_psum1[HCH * NTILES];
__device__ float g_psq1 [HCH * NTILES];
__device__ float g_psum2[HCH * NTILES];
__device__ float g_psq2 [HCH * NTILES];
__device__ float g_scale1[HCH], g_shift1[HCH];
__device__ float g_scale2[HCH], g_shift2[HCH];

// ---------------- three_nn: top-3 NN + inverse-distance weights -------------
__global__ __launch_bounds__(256) void nn_kernel(const float* __restrict__ pos1,
                                                 const float* __restrict__ pos2) {
    __shared__ float sx[SPTS], sy[SPTS], sz[SPTS], sn[SPTS];
    const int b = blockIdx.x >> 5;                    // 32 blocks per batch
    const int n = ((blockIdx.x & 31) << 8) + threadIdx.x;
    const float* p2 = pos2 + b * 3 * SPTS;
    for (int i = threadIdx.x; i < SPTS; i += 256) {
        float x = p2[i], y = p2[SPTS + i], z = p2[2 * SPTS + i];
        sx[i] = x; sy[i] = y; sz[i] = z;
        sn[i] = x * x + y * y + z * z;
    }
    __syncthreads();

    const float* p1 = pos1 + b * 3 * NPTS;
    float x = p1[n], y = p1[NPTS + n], z = p1[2 * NPTS + n];
    float n1 = x * x + y * y + z * z;

    float d0 = 3.4e38f, d1v = 3.4e38f, d2v = 3.4e38f;
    int   i0 = 0, i1 = 0, i2 = 0;
    for (int s = 0; s < SPTS; s++) {
        float dot = x * sx[s] + y * sy[s] + z * sz[s];
        float d = n1 + sn[s] - 2.0f * dot;            // matches reference form
        if (d < d2v) {
            if (d < d1v) {
                d2v = d1v; i2 = i1;
                if (d < d0) { d1v = d0; i1 = i0; d0 = d; i0 = s; }
                else        { d1v = d;  i1 = s; }
            } else { d2v = d; i2 = s; }
        }
    }
    d0  = fmaxf(d0,  1e-10f);
    d1v = fmaxf(d1v, 1e-10f);
    d2v = fmaxf(d2v, 1e-10f);
    float w0 = 1.0f / d0, w1 = 1.0f / d1v, w2 = 1.0f / d2v;
    float inv = 1.0f / (w0 + w1 + w2);
    int base = (b * NPTS + n) * 3;
    g_idx[base] = i0; g_idx[base + 1] = i1; g_idx[base + 2] = i2;
    g_w[base] = w0 * inv; g_w[base + 1] = w1 * inv; g_w[base + 2] = w2 * inv;
}

// ---------------- interpolation gather --------------------------------------
__global__ __launch_bounds__(256) void interp_kernel(const float* __restrict__ f2) {
    int e = blockIdx.x * 256 + threadIdx.x;           // [0, B*D2*NPTS)
    int n = e & (NPTS - 1);
    int d = (e >> 13) & (D2C - 1);
    int b = e >> 21;
    int base = (b * NPTS + n) * 3;
    int j0 = g_idx[base], j1 = g_idx[base + 1], j2 = g_idx[base + 2];
    float w0 = g_w[base], w1 = g_w[base + 1], w2 = g_w[base + 2];
    const float* row = f2 + b * (D2C * SPTS) + d * SPTS;
    g_interp[e] = fmaf(w0, row[j0], fmaf(w1, row[j1], w2 * row[j2]));
}

// ---------------- GEMM1: y1 = W1 @ [interp; feature1] + b1, + BN partials ---
__global__ __launch_bounds__(256) void gemm1_kernel(const float* __restrict__ W1,
                                                    const float* __restrict__ b1,
                                                    const float* __restrict__ feature1) {
    __shared__ float As[16][64];
    __shared__ float Bs[16][64];
    __shared__ float RS[64][16];
    __shared__ float RQ[64][16];

    const int tid = threadIdx.x;
    const int j0  = blockIdx.x * 64;                  // global column
    const int b   = j0 >> 13;
    const int n0  = j0 & (NPTS - 1);
    const int m0  = blockIdx.y * 64;                  // output channel base

    const int am = tid >> 2,  ak = (tid & 3) << 2;    // A-load map
    const int bk = tid >> 4,  bn = (tid & 15) << 2;   // B-load map
    const int ty = tid >> 4,  tx = tid & 15;          // compute map

    const float* interp_b = g_interp + b * (D2C * NPTS);
    const float* f1_b     = feature1 + b * (D1C * NPTS);

    float acc[4][4];
    #pragma unroll
    for (int i = 0; i < 4; i++)
        #pragma unroll
        for (int j = 0; j < 4; j++) acc[i][j] = 0.0f;

    for (int k0 = 0; k0 < CIN; k0 += 16) {
        float4 a4 = *(const float4*)(W1 + (m0 + am) * CIN + k0 + ak);
        As[ak + 0][am] = a4.x; As[ak + 1][am] = a4.y;
        As[ak + 2][am] = a4.z; As[ak + 3][am] = a4.w;
        int c = k0 + bk;
        const float* src = (c < D2C) ? (interp_b + c * NPTS)
                                     : (f1_b + (c - D2C) * NPTS);
        *(float4*)&Bs[bk][bn] = *(const float4*)(src + n0 + bn);
        __syncthreads();
        #pragma unroll
        for (int k = 0; k < 16; k++) {
            float4 av = *(const float4*)&As[k][ty << 2];
            float4 bv = *(const float4*)&Bs[k][tx << 2];
            acc[0][0] = fmaf(av.x, bv.x, acc[0][0]);
            acc[0][1] = fmaf(av.x, bv.y, acc[0][1]);
            acc[0][2] = fmaf(av.x, bv.z, acc[0][2]);
            acc[0][3] = fmaf(av.x, bv.w, acc[0][3]);
            acc[1][0] = fmaf(av.y, bv.x, acc[1][0]);
            acc[1][1] = fmaf(av.y, bv.y, acc[1][1]);
            acc[1][2] = fmaf(av.y, bv.z, acc[1][2]);
            acc[1][3] = fmaf(av.y, bv.w, acc[1][3]);
            acc[2][0] = fmaf(av.z, bv.x, acc[2][0]);
            acc[2][1] = fmaf(av.z, bv.y, acc[2][1]);
            acc[2][2] = fmaf(av.z, bv.z, acc[2][2]);
            acc[2][3] = fmaf(av.z, bv.w, acc[2][3]);
            acc[3][0] = fmaf(av.w, bv.x, acc[3][0]);
            acc[3][1] = fmaf(av.w, bv.y, acc[3][1]);
            acc[3][2] = fmaf(av.w, bv.z, acc[3][2]);
            acc[3][3] = fmaf(av.w, bv.w, acc[3][3]);
        }
        __syncthreads();
    }

    float* y1_b = g_y1 + b * (HCH * NPTS);
    #pragma unroll
    for (int i = 0; i < 4; i++) {
        int o = m0 + (ty << 2) + i;
        float bias = b1[o];
        float4 v;
        v.x = acc[i][0] + bias; v.y = acc[i][1] + bias;
        v.z = acc[i][2] + bias; v.w = acc[i][3] + bias;
        *(float4*)(y1_b + o * NPTS + n0 + (tx << 2)) = v;
        RS[(ty << 2) + i][tx] = v.x + v.y + v.z + v.w;
        RQ[(ty << 2) + i][tx] = v.x * v.x + v.y * v.y + v.z * v.z + v.w * v.w;
    }
    __syncthreads();
    if (tid < 64) {   // deterministic fixed-order reduction
        float s = 0.0f, q = 0.0f;
        #pragma unroll
        for (int t = 0; t < 16; t++) { s += RS[tid][t]; q += RQ[tid][t]; }
        g_psum1[(m0 + tid) * NTILES + blockIdx.x] = s;
        g_psq1 [(m0 + tid) * NTILES + blockIdx.x] = q;
    }
}

// ---------------- BN finalize: scale/shift from partial sums ---------------
__global__ void finalize_kernel(const float* __restrict__ g,
                                const float* __restrict__ be, int layer) {
    int o = threadIdx.x;                              // 256 threads
    const float* ps = (layer == 1) ? g_psum1 : g_psum2;
    const float* pq = (layer == 1) ? g_psq1  : g_psq2;
    float s = 0.0f, q = 0.0f;
    for (int p = 0; p < NTILES; p++) { s += ps[o * NTILES + p]; q += pq[o * NTILES + p]; }
    float mean = s * (1.0f / BN_TOT);
    float var  = q * (1.0f / BN_TOT) - mean * mean;
    float rstd = rsqrtf(var + 1e-5f);
    float sc = g[o] * rstd;
    float sh = be[o] - mean * sc;
    if (layer == 1) { g_scale1[o] = sc; g_shift1[o] = sh; }
    else            { g_scale2[o] = sc; g_shift2[o] = sh; }
}

// ---------------- GEMM2: y2 = W2 @ relu(bn1(y1)) + b2, + BN partials --------
__global__ __launch_bounds__(256) void gemm2_kernel(const float* __restrict__ W2,
                                                    const float* __restrict__ b2,
                                                    float* __restrict__ out) {
    __shared__ float As[16][64];
    __shared__ float Bs[16][64];
    __shared__ float RS[64][16];
    __shared__ float RQ[64][16];

    const int tid = threadIdx.x;
    const int j0  = blockIdx.x * 64;
    const int b   = j0 >> 13;
    const int n0  = j0 & (NPTS - 1);
    const int m0  = blockIdx.y * 64;

    const int am = tid >> 2,  ak = (tid & 3) << 2;
    const int bk = tid >> 4,  bn = (tid & 15) << 2;
    const int ty = tid >> 4,  tx = tid & 15;

    const float* y1_b = g_y1 + b * (HCH * NPTS);

    float acc[4][4];
    #pragma unroll
    for (int i = 0; i < 4; i++)
        #pragma unroll
        for (int j = 0; j < 4; j++) acc[i][j] = 0.0f;

    for (int k0 = 0; k0 < HCH; k0 += 16) {
        float4 a4 = *(const float4*)(W2 + (m0 + am) * HCH + k0 + ak);
        As[ak + 0][am] = a4.x; As[ak + 1][am] = a4.y;
        As[ak + 2][am] = a4.z; As[ak + 3][am] = a4.w;
        int c = k0 + bk;
        float sc = g_scale1[c], sh = g_shift1[c];
        float4 v = *(const float4*)(y1_b + c * NPTS + n0 + bn);
        v.x = fmaxf(fmaf(v.x, sc, sh), 0.0f);
        v.y = fmaxf(fmaf(v.y, sc, sh), 0.0f);
        v.z = fmaxf(fmaf(v.z, sc, sh), 0.0f);
        v.w = fmaxf(fmaf(v.w, sc, sh), 0.0f);
        *(float4*)&Bs[bk][bn] = v;
        __syncthreads();
        #pragma unroll
        for (int k = 0; k < 16; k++) {
            float4 av = *(const float4*)&As[k][ty << 2];
            float4 bv = *(const float4*)&Bs[k][tx << 2];
            acc[0][0] = fmaf(av.x, bv.x, acc[0][0]);
            acc[0][1] = fmaf(av.x, bv.y, acc[0][1]);
            acc[0][2] = fmaf(av.x, bv.z, acc[0][2]);
            acc[0][3] = fmaf(av.x, bv.w, acc[0][3]);
            acc[1][0] = fmaf(av.y, bv.x, acc[1][0]);
            acc[1][1] = fmaf(av.y, bv.y, acc[1][1]);
            acc[1][2] = fmaf(av.y, bv.z, acc[1][2]);
            acc[1][3] = fmaf(av.y, bv.w, acc[1][3]);
            acc[2][0] = fmaf(av.z, bv.x, acc[2][0]);
            acc[2][1] = fmaf(av.z, bv.y, acc[2][1]);
            acc[2][2] = fmaf(av.z, bv.z, acc[2][2]);
            acc[2][3] = fmaf(av.z, bv.w, acc[2][3]);
            acc[3][0] = fmaf(av.w, bv.x, acc[3][0]);
            acc[3][1] = fmaf(av.w, bv.y, acc[3][1]);
            acc[3][2] = fmaf(av.w, bv.z, acc[3][2]);
            acc[3][3] = fmaf(av.w, bv.w, acc[3][3]);
        }
        __syncthreads();
    }

    float* out_b = out + b * (HCH * NPTS);
    #pragma unroll
    for (int i = 0; i < 4; i++) {
        int o = m0 + (ty << 2) + i;
        float bias = b2[o];
        float4 v;
        v.x = acc[i][0] + bias; v.y = acc[i][1] + bias;
        v.z = acc[i][2] + bias; v.w = acc[i][3] + bias;
        *(float4*)(out_b + o * NPTS + n0 + (tx << 2)) = v;
        RS[(ty << 2) + i][tx] = v.x + v.y + v.z + v.w;
        RQ[(ty << 2) + i][tx] = v.x * v.x + v.y * v.y + v.z * v.z + v.w * v.w;
    }
    __syncthreads();
    if (tid < 64) {
        float s = 0.0f, q = 0.0f;
        #pragma unroll
        for (int t = 0; t < 16; t++) { s += RS[tid][t]; q += RQ[tid][t]; }
        g_psum2[(m0 + tid) * NTILES + blockIdx.x] = s;
        g_psq2 [(m0 + tid) * NTILES + blockIdx.x] = q;
    }
}

// ---------------- final BN2 + ReLU over d_out -------------------------------
__global__ __launch_bounds__(1024) void bnrelu_kernel(float* __restrict__ out) {
    int e = blockIdx.x * 1024 + threadIdx.x;
    int o = (e >> 13) & (HCH - 1);
    out[e] = fmaxf(fmaf(out[e], g_scale2[o], g_shift2[o]), 0.0f);
}

// ---------------- launch ----------------------------------------------------
extern "C" void kernel_launch(void* const* d_in, const int* in_sizes, int n_in,
                              void* d_out, int out_size) {
    const float* pos1     = (const float*)d_in[0];
    const float* pos2     = (const float*)d_in[1];
    const float* feature1 = (const float*)d_in[2];
    const float* feature2 = (const float*)d_in[3];
    const float* W1 = (const float*)d_in[4];
    const float* b1 = (const float*)d_in[5];
    const float* g1 = (const float*)d_in[6];
    const float* be1 = (const float*)d_in[7];
    const float* W2 = (const float*)d_in[8];
    const float* b2 = (const float*)d_in[9];
    const float* g2 = (const float*)d_in[10];
    const float* be2 = (const float*)d_in[11];
    float* out = (float*)d_out;

    nn_kernel<<<BATCH * 32, 256>>>(pos1, pos2);
    interp_kernel<<<(BATCH * D2C * NPTS) / 256, 256>>>(feature2);
    gemm1_kernel<<<dim3(NTILES, HCH / 64), 256>>>(W1, b1, feature1);
    finalize_kernel<<<1, 256>>>(g1, be1, 1);
    gemm2_kernel<<<dim3(NTILES, HCH / 64), 256>>>(W2, b2, out);
    finalize_kernel<<<1, 256>>>(g2, be2, 2);
    bnrelu_kernel<<<(BATCH * HCH * NPTS) / 1024, 1024>>>(out);
}

// round 6
// speedup vs baseline: 1.1872x; 1.1872x over previous
#include <cuda_runtime.h>

#define BATCH 4
#define NPTS  8192
#define SPTS  2048
#define D1C   128
#define D2C   256
#define CIN   384
#define HCH   256
#define BN_TOT (BATCH * NPTS)   // 32768
#define NT    256               // (BATCH*NPTS)/128 column tiles

// ---------------- scratch (static device globals; no allocation allowed) ----
__device__ int   g_idx[BATCH * NPTS * 3];
__device__ float g_w[BATCH * NPTS * 3];
__device__ float g_interp[BATCH * D2C * NPTS];   // 32 MB
__device__ float g_y1[BATCH * HCH * NPTS];       // 32 MB
__device__ float g_psum1[HCH * NT];
__device__ float g_psq1 [HCH * NT];
__device__ float g_psum2[HCH * NT];
__device__ float g_psq2 [HCH * NT];
__device__ float g_scale1[HCH], g_shift1[HCH];
__device__ float g_scale2[HCH], g_shift2[HCH];

// packed fp32x2 helpers (Blackwell FFMA2 path — only reachable via PTX)
__device__ __forceinline__ unsigned long long pack2(float v) {
    unsigned long long r;
    asm("mov.b64 %0, {%1, %1};" : "=l"(r) : "r"(__float_as_uint(v)));
    return r;
}
__device__ __forceinline__ void fma2(unsigned long long& d,
                                     unsigned long long a, unsigned long long b) {
    asm("fma.rn.f32x2 %0, %1, %2, %3;" : "=l"(d) : "l"(a), "l"(b), "l"(d));
}
__device__ __forceinline__ void unpack2(unsigned long long v, float& lo, float& hi) {
    unsigned int a, b;
    asm("mov.b64 {%0, %1}, %2;" : "=r"(a), "=r"(b) : "l"(v));
    lo = __uint_as_float(a); hi = __uint_as_float(b);
}

// ---------------- three_nn: top-3 NN + inverse-distance weights -------------
__global__ __launch_bounds__(256) void nn_kernel(const float* __restrict__ pos1,
                                                 const float* __restrict__ pos2) {
    __shared__ float sx[SPTS], sy[SPTS], sz[SPTS], sn[SPTS];
    const int b = blockIdx.x >> 5;                    // 32 blocks per batch
    const int n = ((blockIdx.x & 31) << 8) + threadIdx.x;
    const float* p2 = pos2 + b * 3 * SPTS;
    for (int i = threadIdx.x; i < SPTS; i += 256) {
        float x = p2[i], y = p2[SPTS + i], z = p2[2 * SPTS + i];
        sx[i] = x; sy[i] = y; sz[i] = z;
        sn[i] = x * x + y * y + z * z;
    }
    __syncthreads();

    const float* p1 = pos1 + b * 3 * NPTS;
    float x = p1[n], y = p1[NPTS + n], z = p1[2 * NPTS + n];
    float n1 = x * x + y * y + z * z;

    float d0 = 3.4e38f, d1v = 3.4e38f, d2v = 3.4e38f;
    int   i0 = 0, i1 = 0, i2 = 0;
    for (int s = 0; s < SPTS; s++) {
        float dot = x * sx[s] + y * sy[s] + z * sz[s];
        float d = n1 + sn[s] - 2.0f * dot;            // matches reference form
        if (d < d2v) {
            if (d < d1v) {
                d2v = d1v; i2 = i1;
                if (d < d0) { d1v = d0; i1 = i0; d0 = d; i0 = s; }
                else        { d1v = d;  i1 = s; }
            } else { d2v = d; i2 = s; }
        }
    }
    d0  = fmaxf(d0,  1e-10f);
    d1v = fmaxf(d1v, 1e-10f);
    d2v = fmaxf(d2v, 1e-10f);
    float w0 = 1.0f / d0, w1 = 1.0f / d1v, w2 = 1.0f / d2v;
    float inv = 1.0f / (w0 + w1 + w2);
    int base = (b * NPTS + n) * 3;
    g_idx[base] = i0; g_idx[base + 1] = i1; g_idx[base + 2] = i2;
    g_w[base] = w0 * inv; g_w[base + 1] = w1 * inv; g_w[base + 2] = w2 * inv;
}

// ---------------- interpolation gather --------------------------------------
__global__ __launch_bounds__(256) void interp_kernel(const float* __restrict__ f2) {
    int e = blockIdx.x * 256 + threadIdx.x;           // [0, B*D2*NPTS)
    int n = e & (NPTS - 1);
    int d = (e >> 13) & (D2C - 1);
    int b = e >> 21;
    int base = (b * NPTS + n) * 3;
    int j0 = g_idx[base], j1 = g_idx[base + 1], j2 = g_idx[base + 2];
    float w0 = g_w[base], w1 = g_w[base + 1], w2 = g_w[base + 2];
    const float* row = f2 + b * (D2C * SPTS) + d * SPTS;
    g_interp[e] = fmaf(w0, row[j0], fmaf(w1, row[j1], w2 * row[j2]));
}

// ---------------- GEMM core macro body: 64x128 tile, 4x8 micro, FFMA2 -------
// LAYER=1: B from [interp; feature1]; LAYER=2: B = relu(bn1(y1))
template <int LAYER>
__global__ __launch_bounds__(256) void gemm_kernel(const float* __restrict__ W,
                                                   const float* __restrict__ bias_v,
                                                   const float* __restrict__ feature1,
                                                   float* __restrict__ outp) {
    __shared__ float As[16][64];
    __shared__ float Bs[16][128];
    __shared__ float RS[64][16];
    __shared__ float RQ[64][16];

    const int tid = threadIdx.x;
    const int j0  = blockIdx.x * 128;                 // global column
    const int b   = j0 >> 13;
    const int n0  = j0 & (NPTS - 1);
    const int m0  = blockIdx.y * 64;                  // output channel base

    const int am = tid >> 2,  ak = (tid & 3) << 2;    // A-load map
    const int bk = tid >> 4,  bn = (tid & 15) << 3;   // B-load map (8 floats)
    const int ty = tid >> 4,  tx = tid & 15;          // compute map

    const float* interp_b = g_interp + b * (D2C * NPTS);
    const float* f1_b     = feature1 + b * (D1C * NPTS);
    const float* y1_b     = g_y1 + b * (HCH * NPTS);

    const int KDIM = (LAYER == 1) ? CIN : HCH;

    unsigned long long acc[4][4];                     // 4 rows x 4 packed col-pairs
    #pragma unroll
    for (int i = 0; i < 4; i++)
        #pragma unroll
        for (int j = 0; j < 4; j++) acc[i][j] = 0ULL;

    for (int k0 = 0; k0 < KDIM; k0 += 16) {
        float4 a4 = *(const float4*)(W + (m0 + am) * KDIM + k0 + ak);
        As[ak + 0][am] = a4.x; As[ak + 1][am] = a4.y;
        As[ak + 2][am] = a4.z; As[ak + 3][am] = a4.w;

        int c = k0 + bk;
        if (LAYER == 1) {
            const float* src = (c < D2C) ? (interp_b + c * NPTS)
                                         : (f1_b + (c - D2C) * NPTS);
            *(float4*)&Bs[bk][bn]     = *(const float4*)(src + n0 + bn);
            *(float4*)&Bs[bk][bn + 4] = *(const float4*)(src + n0 + bn + 4);
        } else {
            float sc = g_scale1[c], sh = g_shift1[c];
            float4 v0 = *(const float4*)(y1_b + c * NPTS + n0 + bn);
            float4 v1 = *(const float4*)(y1_b + c * NPTS + n0 + bn + 4);
            v0.x = fmaxf(fmaf(v0.x, sc, sh), 0.0f);
            v0.y = fmaxf(fmaf(v0.y, sc, sh), 0.0f);
            v0.z = fmaxf(fmaf(v0.z, sc, sh), 0.0f);
            v0.w = fmaxf(fmaf(v0.w, sc, sh), 0.0f);
            v1.x = fmaxf(fmaf(v1.x, sc, sh), 0.0f);
            v1.y = fmaxf(fmaf(v1.y, sc, sh), 0.0f);
            v1.z = fmaxf(fmaf(v1.z, sc, sh), 0.0f);
            v1.w = fmaxf(fmaf(v1.w, sc, sh), 0.0f);
            *(float4*)&Bs[bk][bn]     = v0;
            *(float4*)&Bs[bk][bn + 4] = v1;
        }
        __syncthreads();

        #pragma unroll
        for (int k = 0; k < 16; k++) {
            float4 av = *(const float4*)&As[k][ty << 2];
            const unsigned long long* bp =
                (const unsigned long long*)&Bs[k][tx << 3];
            unsigned long long bq0 = bp[0], bq1 = bp[1], bq2 = bp[2], bq3 = bp[3];
            unsigned long long a0 = pack2(av.x), a1 = pack2(av.y),
                               a2 = pack2(av.z), a3 = pack2(av.w);
            fma2(acc[0][0], a0, bq0); fma2(acc[0][1], a0, bq1);
            fma2(acc[0][2], a0, bq2); fma2(acc[0][3], a0, bq3);
            fma2(acc[1][0], a1, bq0); fma2(acc[1][1], a1, bq1);
            fma2(acc[1][2], a1, bq2); fma2(acc[1][3], a1, bq3);
            fma2(acc[2][0], a2, bq0); fma2(acc[2][1], a2, bq1);
            fma2(acc[2][2], a2, bq2); fma2(acc[2][3], a2, bq3);
            fma2(acc[3][0], a3, bq0); fma2(acc[3][1], a3, bq1);
            fma2(acc[3][2], a3, bq2); fma2(acc[3][3], a3, bq3);
        }
        __syncthreads();
    }

    float* out_b = (LAYER == 1) ? (g_y1 + b * (HCH * NPTS))
                                : (outp + b * (HCH * NPTS));
    float* psum = (LAYER == 1) ? g_psum1 : g_psum2;
    float* psq  = (LAYER == 1) ? g_psq1  : g_psq2;

    #pragma unroll
    for (int i = 0; i < 4; i++) {
        int o = m0 + (ty << 2) + i;
        float bv = bias_v[o];
        float f[8];
        unpack2(acc[i][0], f[0], f[1]);
        unpack2(acc[i][1], f[2], f[3]);
        unpack2(acc[i][2], f[4], f[5]);
        unpack2(acc[i][3], f[6], f[7]);
        float s = 0.0f, q = 0.0f;
        #pragma unroll
        for (int j = 0; j < 8; j++) { f[j] += bv; s += f[j]; q += f[j] * f[j]; }
        float4 v0 = make_float4(f[0], f[1], f[2], f[3]);
        float4 v1 = make_float4(f[4], f[5], f[6], f[7]);
        *(float4*)(out_b + o * NPTS + n0 + (tx << 3))     = v0;
        *(float4*)(out_b + o * NPTS + n0 + (tx << 3) + 4) = v1;
        RS[(ty << 2) + i][tx] = s;
        RQ[(ty << 2) + i][tx] = q;
    }
    __syncthreads();
    if (tid < 64) {   // deterministic fixed-order reduction
        float s = 0.0f, q = 0.0f;
        #pragma unroll
        for (int t = 0; t < 16; t++) { s += RS[tid][t]; q += RQ[tid][t]; }
        psum[(m0 + tid) * NT + blockIdx.x] = s;
        psq [(m0 + tid) * NT + blockIdx.x] = q;
    }
}

// ---------------- BN finalize: one block per channel, tree reduction --------
__global__ __launch_bounds__(128) void finalize_kernel(const float* __restrict__ g,
                                                       const float* __restrict__ be,
                                                       int layer) {
    __shared__ float ss[128], sq[128];
    const int o = blockIdx.x;
    const int t = threadIdx.x;
    const float* ps = (layer == 1) ? g_psum1 : g_psum2;
    const float* pq = (layer == 1) ? g_psq1  : g_psq2;
    float s = ps[o * NT + t] + ps[o * NT + t + 128];
    float q = pq[o * NT + t] + pq[o * NT + t + 128];
    ss[t] = s; sq[t] = q;
    __syncthreads();
    #pragma unroll
    for (int off = 64; off > 0; off >>= 1) {
        if (t < off) { ss[t] += ss[t + off]; sq[t] += sq[t + off]; }
        __syncthreads();
    }
    if (t == 0) {
        float mean = ss[0] * (1.0f / BN_TOT);
        float var  = sq[0] * (1.0f / BN_TOT) - mean * mean;
        float rstd = rsqrtf(var + 1e-5f);
        float sc = g[o] * rstd;
        float sh = be[o] - mean * sc;
        if (layer == 1) { g_scale1[o] = sc; g_shift1[o] = sh; }
        else            { g_scale2[o] = sc; g_shift2[o] = sh; }
    }
}

// ---------------- final BN2 + ReLU over d_out -------------------------------
__global__ __launch_bounds__(1024) void bnrelu_kernel(float* __restrict__ out) {
    int e = blockIdx.x * 1024 + threadIdx.x;
    int o = (e >> 13) & (HCH - 1);
    out[e] = fmaxf(fmaf(out[e], g_scale2[o], g_shift2[o]), 0.0f);
}

// ---------------- launch ----------------------------------------------------
extern "C" void kernel_launch(void* const* d_in, const int* in_sizes, int n_in,
                              void* d_out, int out_size) {
    const float* pos1     = (const float*)d_in[0];
    const float* pos2     = (const float*)d_in[1];
    const float* feature1 = (const float*)d_in[2];
    const float* feature2 = (const float*)d_in[3];
    const float* W1 = (const float*)d_in[4];
    const float* b1 = (const float*)d_in[5];
    const float* g1 = (const float*)d_in[6];
    const float* be1 = (const float*)d_in[7];
    const float* W2 = (const float*)d_in[8];
    const float* b2 = (const float*)d_in[9];
    const float* g2 = (const float*)d_in[10];
    const float* be2 = (const float*)d_in[11];
    float* out = (float*)d_out;

    nn_kernel<<<BATCH * 32, 256>>>(pos1, pos2);
    interp_kernel<<<(BATCH * D2C * NPTS) / 256, 256>>>(feature2);
    gemm_kernel<1><<<dim3(NT, HCH / 64), 256>>>(W1, b1, feature1, out);
    finalize_kernel<<<HCH, 128>>>(g1, be1, 1);
    gemm_kernel<2><<<dim3(NT, HCH / 64), 256>>>(W2, b2, feature1, out);
    finalize_kernel<<<HCH, 128>>>(g2, be2, 2);
    bnrelu_kernel<<<(BATCH * HCH * NPTS) / 1024, 1024>>>(out);
}

// round 9
// speedup vs baseline: 1.5816x; 1.3322x over previous
#include <cuda_runtime.h>

#define BATCH 4
#define NPTS  8192
#define SPTS  2048
#define D1C   128
#define D2C   256
#define CIN   384
#define HCH   256
#define BN_TOT (BATCH * NPTS)   // 32768
#define NT    256               // (BATCH*NPTS)/128 column tiles

// ---------------- scratch (static device globals; no allocation allowed) ----
__device__ int   g_idx[BATCH * NPTS * 3];
__device__ float g_w[BATCH * NPTS * 3];
__device__ float g_zt[BATCH * SPTS * HCH];       // Z^T: [b][s][o], 8 MB
__device__ float g_y1[BATCH * HCH * NPTS];       // 32 MB
__device__ float g_psum1[HCH * NT];
__device__ float g_psq1 [HCH * NT];
__device__ float g_psum2[HCH * NT];
__device__ float g_psq2 [HCH * NT];
__device__ float g_scale1[HCH], g_shift1[HCH];
__device__ float g_scale2[HCH], g_shift2[HCH];

// ---------------- three_nn: top-3 NN + inverse-distance weights -------------
__global__ __launch_bounds__(256) void nn_kernel(const float* __restrict__ pos1,
                                                 const float* __restrict__ pos2) {
    __shared__ float sx[SPTS], sy[SPTS], sz[SPTS], sn[SPTS];
    const int b = blockIdx.x >> 5;                    // 32 blocks per batch
    const int n = ((blockIdx.x & 31) << 8) + threadIdx.x;
    const float* p2 = pos2 + b * 3 * SPTS;
    for (int i = threadIdx.x; i < SPTS; i += 256) {
        float x = p2[i], y = p2[SPTS + i], z = p2[2 * SPTS + i];
        sx[i] = x; sy[i] = y; sz[i] = z;
        sn[i] = x * x + y * y + z * z;
    }
    __syncthreads();

    const float* p1 = pos1 + b * 3 * NPTS;
    float x = p1[n], y = p1[NPTS + n], z = p1[2 * NPTS + n];
    float n1 = x * x + y * y + z * z;

    float d0 = 3.4e38f, d1v = 3.4e38f, d2v = 3.4e38f;
    int   i0 = 0, i1 = 0, i2 = 0;
    for (int s = 0; s < SPTS; s++) {
        float dot = x * sx[s] + y * sy[s] + z * sz[s];
        float d = n1 + sn[s] - 2.0f * dot;            // matches reference form
        if (d < d2v) {
            if (d < d1v) {
                d2v = d1v; i2 = i1;
                if (d < d0) { d1v = d0; i1 = i0; d0 = d; i0 = s; }
                else        { d1v = d;  i1 = s; }
            } else { d2v = d; i2 = s; }
        }
    }
    d0  = fmaxf(d0,  1e-10f);
    d1v = fmaxf(d1v, 1e-10f);
    d2v = fmaxf(d2v, 1e-10f);
    float w0 = 1.0f / d0, w1 = 1.0f / d1v, w2 = 1.0f / d2v;
    float inv = 1.0f / (w0 + w1 + w2);
    int base = (b * NPTS + n) * 3;
    g_idx[base] = i0; g_idx[base + 1] = i1; g_idx[base + 2] = i2;
    g_w[base] = w0 * inv; g_w[base + 1] = w1 * inv; g_w[base + 2] = w2 * inv;
}

// ---------------- unified GEMM: 64x128 tile, 4x8 micro, scalar FFMA ---------
// MODE 0: Z^T = (W1[:, :256] @ feature2)^T        (KDIM=256, cols=SPTS)
// MODE 1: y1  = W1[:, 256:] @ feature1 + gather(Z^T) + b1, BN partials
// MODE 2: out = W2 @ relu(bn1(y1)) + b2, BN partials  (B read from g_y1 symbol)
template <int MODE>
__global__ __launch_bounds__(256) void gemm_kernel(const float* __restrict__ A,
                                                   const float* __restrict__ bias_v,
                                                   const float* __restrict__ Bsrc,
                                                   float* __restrict__ outp) {
    __shared__ float As[16][64];
    __shared__ float Bs[16][128];
    __shared__ float RS[64][16];
    __shared__ float RQ[64][16];

    const int KDIM    = (MODE == 0) ? D2C : (MODE == 1) ? D1C : HCH;
    const int ASTRIDE = (MODE == 2) ? HCH : CIN;
    const int COLS    = (MODE == 0) ? SPTS : NPTS;

    const int tid = threadIdx.x;
    const int b   = (MODE == 0) ? (blockIdx.x >> 4) : (blockIdx.x >> 6);
    const int n0  = (MODE == 0) ? ((blockIdx.x & 15) << 7)
                                : ((blockIdx.x & 63) << 7);
    const int m0  = blockIdx.y * 64;                  // output channel base

    const int am = tid >> 2,  ak = (tid & 3) << 2;    // A-load map
    const int bk = tid >> 4,  bn = (tid & 15) << 3;   // B-load map (8 floats)
    const int ty = tid >> 4,  tx = tid & 15;          // compute map

    // MODE 2 must read its B from the device symbol, not a host-passed pointer.
    const float* B_b = (MODE == 2)
        ? (g_y1 + (long long)b * KDIM * COLS)
        : (Bsrc + (long long)b * KDIM * COLS);

    float acc[4][8];
    #pragma unroll
    for (int i = 0; i < 4; i++)
        #pragma unroll
        for (int j = 0; j < 8; j++) acc[i][j] = 0.0f;

    for (int k0 = 0; k0 < KDIM; k0 += 16) {
        float4 a4 = *(const float4*)(A + (m0 + am) * ASTRIDE + k0 + ak);
        As[ak + 0][am] = a4.x; As[ak + 1][am] = a4.y;
        As[ak + 2][am] = a4.z; As[ak + 3][am] = a4.w;

        const int c = k0 + bk;
        const float* src = B_b + (long long)c * COLS + n0 + bn;
        if (MODE == 2) {
            float sc = g_scale1[c], sh = g_shift1[c];
            float4 v0 = *(const float4*)(src);
            float4 v1 = *(const float4*)(src + 4);
            v0.x = fmaxf(fmaf(v0.x, sc, sh), 0.0f);
            v0.y = fmaxf(fmaf(v0.y, sc, sh), 0.0f);
            v0.z = fmaxf(fmaf(v0.z, sc, sh), 0.0f);
            v0.w = fmaxf(fmaf(v0.w, sc, sh), 0.0f);
            v1.x = fmaxf(fmaf(v1.x, sc, sh), 0.0f);
            v1.y = fmaxf(fmaf(v1.y, sc, sh), 0.0f);
            v1.z = fmaxf(fmaf(v1.z, sc, sh), 0.0f);
            v1.w = fmaxf(fmaf(v1.w, sc, sh), 0.0f);
            *(float4*)&Bs[bk][bn]     = v0;
            *(float4*)&Bs[bk][bn + 4] = v1;
        } else {
            *(float4*)&Bs[bk][bn]     = *(const float4*)(src);
            *(float4*)&Bs[bk][bn + 4] = *(const float4*)(src + 4);
        }
        __syncthreads();

        #pragma unroll
        for (int k = 0; k < 16; k++) {
            float4 av = *(const float4*)&As[k][ty << 2];
            float4 b0 = *(const float4*)&Bs[k][tx << 3];
            float4 b1 = *(const float4*)&Bs[k][(tx << 3) + 4];
            acc[0][0] = fmaf(av.x, b0.x, acc[0][0]);
            acc[0][1] = fmaf(av.x, b0.y, acc[0][1]);
            acc[0][2] = fmaf(av.x, b0.z, acc[0][2]);
            acc[0][3] = fmaf(av.x, b0.w, acc[0][3]);
            acc[0][4] = fmaf(av.x, b1.x, acc[0][4]);
            acc[0][5] = fmaf(av.x, b1.y, acc[0][5]);
            acc[0][6] = fmaf(av.x, b1.z, acc[0][6]);
            acc[0][7] = fmaf(av.x, b1.w, acc[0][7]);
            acc[1][0] = fmaf(av.y, b0.x, acc[1][0]);
            acc[1][1] = fmaf(av.y, b0.y, acc[1][1]);
            acc[1][2] = fmaf(av.y, b0.z, acc[1][2]);
            acc[1][3] = fmaf(av.y, b0.w, acc[1][3]);
            acc[1][4] = fmaf(av.y, b1.x, acc[1][4]);
            acc[1][5] = fmaf(av.y, b1.y, acc[1][5]);
            acc[1][6] = fmaf(av.y, b1.z, acc[1][6]);
            acc[1][7] = fmaf(av.y, b1.w, acc[1][7]);
            acc[2][0] = fmaf(av.z, b0.x, acc[2][0]);
            acc[2][1] = fmaf(av.z, b0.y, acc[2][1]);
            acc[2][2] = fmaf(av.z, b0.z, acc[2][2]);
            acc[2][3] = fmaf(av.z, b0.w, acc[2][3]);
            acc[2][4] = fmaf(av.z, b1.x, acc[2][4]);
            acc[2][5] = fmaf(av.z, b1.y, acc[2][5]);
            acc[2][6] = fmaf(av.z, b1.z, acc[2][6]);
            acc[2][7] = fmaf(av.z, b1.w, acc[2][7]);
            acc[3][0] = fmaf(av.w, b0.x, acc[3][0]);
            acc[3][1] = fmaf(av.w, b0.y, acc[3][1]);
            acc[3][2] = fmaf(av.w, b0.z, acc[3][2]);
            acc[3][3] = fmaf(av.w, b0.w, acc[3][3]);
            acc[3][4] = fmaf(av.w, b1.x, acc[3][4]);
            acc[3][5] = fmaf(av.w, b1.y, acc[3][5]);
            acc[3][6] = fmaf(av.w, b1.z, acc[3][6]);
            acc[3][7] = fmaf(av.w, b1.w, acc[3][7]);
        }
        __syncthreads();
    }

    if (MODE == 0) {
        // transposed store: Z^T[b][s][o], contiguous float4 over o
        float* zt_b = g_zt + b * (SPTS * HCH);
        #pragma unroll
        for (int jj = 0; jj < 8; jj++) {
            int s = n0 + (tx << 3) + jj;
            float4 v = make_float4(acc[0][jj], acc[1][jj], acc[2][jj], acc[3][jj]);
            *(float4*)(zt_b + s * HCH + m0 + (ty << 2)) = v;
        }
        return;
    }

    if (MODE == 1) {
        // add interpolated contribution: sum_j w_j * Z^T[idx_j][o]
        const float* zt_b = g_zt + b * (SPTS * HCH);
        const int o_base = m0 + (ty << 2);
        #pragma unroll
        for (int jj = 0; jj < 8; jj++) {
            int n = n0 + (tx << 3) + jj;
            int base = (b * NPTS + n) * 3;
            int j0i = g_idx[base], j1i = g_idx[base + 1], j2i = g_idx[base + 2];
            float w0 = g_w[base], w1 = g_w[base + 1], w2 = g_w[base + 2];
            float4 z0 = *(const float4*)(zt_b + j0i * HCH + o_base);
            float4 z1 = *(const float4*)(zt_b + j1i * HCH + o_base);
            float4 z2 = *(const float4*)(zt_b + j2i * HCH + o_base);
            acc[0][jj] += w0 * z0.x + w1 * z1.x + w2 * z2.x;
            acc[1][jj] += w0 * z0.y + w1 * z1.y + w2 * z2.y;
            acc[2][jj] += w0 * z0.z + w1 * z1.z + w2 * z2.z;
            acc[3][jj] += w0 * z0.w + w1 * z1.w + w2 * z2.w;
        }
    }

    float* out_b = (MODE == 1) ? (g_y1 + b * (HCH * NPTS))
                               : (outp + b * (HCH * NPTS));
    float* psum = (MODE == 1) ? g_psum1 : g_psum2;
    float* psq  = (MODE == 1) ? g_psq1  : g_psq2;

    #pragma unroll
    for (int i = 0; i < 4; i++) {
        int o = m0 + (ty << 2) + i;
        float bv = bias_v[o];
        float s = 0.0f, q = 0.0f;
        #pragma unroll
        for (int j = 0; j < 8; j++) {
            acc[i][j] += bv;
            s += acc[i][j];
            q += acc[i][j] * acc[i][j];
        }
        float4 v0 = make_float4(acc[i][0], acc[i][1], acc[i][2], acc[i][3]);
        float4 v1 = make_float4(acc[i][4], acc[i][5], acc[i][6], acc[i][7]);
        *(float4*)(out_b + o * NPTS + n0 + (tx << 3))     = v0;
        *(float4*)(out_b + o * NPTS + n0 + (tx << 3) + 4) = v1;
        RS[(ty << 2) + i][tx] = s;
        RQ[(ty << 2) + i][tx] = q;
    }
    __syncthreads();
    if (tid < 64) {   // deterministic fixed-order reduction
        float s = 0.0f, q = 0.0f;
        #pragma unroll
        for (int t = 0; t < 16; t++) { s += RS[tid][t]; q += RQ[tid][t]; }
        psum[(m0 + tid) * NT + blockIdx.x] = s;
        psq [(m0 + tid) * NT + blockIdx.x] = q;
    }
}

// ---------------- BN finalize: one block per channel, tree reduction --------
__global__ __launch_bounds__(128) void finalize_kernel(const float* __restrict__ g,
                                                       const float* __restrict__ be,
                                                       int layer) {
    __shared__ float ss[128], sq[128];
    const int o = blockIdx.x;
    const int t = threadIdx.x;
    const float* ps = (layer == 1) ? g_psum1 : g_psum2;
    const float* pq = (layer == 1) ? g_psq1  : g_psq2;
    float s = ps[o * NT + t] + ps[o * NT + t + 128];
    float q = pq[o * NT + t] + pq[o * NT + t + 128];
    ss[t] = s; sq[t] = q;
    __syncthreads();
    #pragma unroll
    for (int off = 64; off > 0; off >>= 1) {
        if (t < off) { ss[t] += ss[t + off]; sq[t] += sq[t + off]; }
        __syncthreads();
    }
    if (t == 0) {
        float mean = ss[0] * (1.0f / BN_TOT);
        float var  = sq[0] * (1.0f / BN_TOT) - mean * mean;
        float rstd = rsqrtf(var + 1e-5f);
        float sc = g[o] * rstd;
        float sh = be[o] - mean * sc;
        if (layer == 1) { g_scale1[o] = sc; g_shift1[o] = sh; }
        else            { g_scale2[o] = sc; g_shift2[o] = sh; }
    }
}

// ---------------- final BN2 + ReLU over d_out -------------------------------
__global__ __launch_bounds__(1024) void bnrelu_kernel(float* __restrict__ out) {
    int e = blockIdx.x * 1024 + threadIdx.x;
    int o = (e >> 13) & (HCH - 1);
    out[e] = fmaxf(fmaf(out[e], g_scale2[o], g_shift2[o]), 0.0f);
}

// ---------------- launch ----------------------------------------------------
extern "C" void kernel_launch(void* const* d_in, const int* in_sizes, int n_in,
                              void* d_out, int out_size) {
    const float* pos1     = (const float*)d_in[0];
    const float* pos2     = (const float*)d_in[1];
    const float* feature1 = (const float*)d_in[2];
    const float* feature2 = (const float*)d_in[3];
    const float* W1 = (const float*)d_in[4];
    const float* b1 = (const float*)d_in[5];
    const float* g1 = (const float*)d_in[6];
    const float* be1 = (const float*)d_in[7];
    const float* W2 = (const float*)d_in[8];
    const float* b2 = (const float*)d_in[9];
    const float* g2 = (const float*)d_in[10];
    const float* be2 = (const float*)d_in[11];
    float* out = (float*)d_out;

    nn_kernel<<<BATCH * 32, 256>>>(pos1, pos2);
    // Z^T = (W1[:, :256] @ feature2)^T : 16 col-tiles per batch, 4 m-tiles
    gemm_kernel<0><<<dim3(BATCH * 16, HCH / 64), 256>>>(W1, b1, feature2, out);
    // y1 = W1[:, 256:] @ feature1 + gather(Z^T) + b1
    gemm_kernel<1><<<dim3(NT, HCH / 64), 256>>>(W1 + D2C, b1, feature1, out);
    finalize_kernel<<<HCH, 128>>>(g1, be1, 1);
    // MODE 2 reads its B from the g_y1 device symbol internally
    gemm_kernel<2><<<dim3(NT, HCH / 64), 256>>>(W2, b2, feature1, out);
    finalize_kernel<<<HCH, 128>>>(g2, be2, 2);
    bnrelu_kernel<<<(BATCH * HCH * NPTS) / 1024, 1024>>>(out);
}

// round 11
// speedup vs baseline: 2.0857x; 1.3187x over previous
#include <cuda_runtime.h>

#define BATCH 4
#define NPTS  8192
#define SPTS  2048
#define D1C   128
#define D2C   256
#define CIN   384
#define HCH   256
#define BN_TOT (BATCH * NPTS)   // 32768
#define NT    256               // (BATCH*NPTS)/128 column tiles

// ---------------- scratch (static device globals; no allocation allowed) ----
__device__ int   g_idx[BATCH * NPTS * 3];
__device__ float g_w[BATCH * NPTS * 3];
__device__ float g_zt[BATCH * SPTS * HCH];       // Z^T: [b][s][o], 8 MB
__device__ float g_y1[BATCH * HCH * NPTS];       // 32 MB
__device__ float g_psum1[HCH * NT];
__device__ float g_psq1 [HCH * NT];
__device__ float g_psum2[HCH * NT];
__device__ float g_psq2 [HCH * NT];
__device__ float g_scale1[HCH], g_shift1[HCH];
__device__ float g_scale2[HCH], g_shift2[HCH];

// ---------------- tf32 helpers ----------------------------------------------
__device__ __forceinline__ void split_tf32(float x, unsigned& hi, unsigned& lo) {
    unsigned h;
    asm("cvt.rna.tf32.f32 %0, %1;" : "=r"(h) : "f"(x));
    float l = x - __uint_as_float(h);
    unsigned lt;
    asm("cvt.rna.tf32.f32 %0, %1;" : "=r"(lt) : "f"(l));
    hi = h; lo = lt;
}
__device__ __forceinline__ void mma8(float* d, const unsigned* a, const unsigned* b) {
    asm volatile(
        "mma.sync.aligned.m16n8k8.row.col.f32.tf32.tf32.f32 "
        "{%0,%1,%2,%3}, {%4,%5,%6,%7}, {%8,%9}, {%0,%1,%2,%3};"
        : "+f"(d[0]), "+f"(d[1]), "+f"(d[2]), "+f"(d[3])
        : "r"(a[0]), "r"(a[1]), "r"(a[2]), "r"(a[3]), "r"(b[0]), "r"(b[1]));
}

// ---------------- three_nn: top-3 NN + inverse-distance weights -------------
__global__ __launch_bounds__(256) void nn_kernel(const float* __restrict__ pos1,
                                                 const float* __restrict__ pos2) {
    __shared__ float sx[SPTS], sy[SPTS], sz[SPTS], sn[SPTS];
    const int b = blockIdx.x >> 5;                    // 32 blocks per batch
    const int n = ((blockIdx.x & 31) << 8) + threadIdx.x;
    const float* p2 = pos2 + b * 3 * SPTS;
    for (int i = threadIdx.x; i < SPTS; i += 256) {
        float x = p2[i], y = p2[SPTS + i], z = p2[2 * SPTS + i];
        sx[i] = x; sy[i] = y; sz[i] = z;
        sn[i] = x * x + y * y + z * z;
    }
    __syncthreads();

    const float* p1 = pos1 + b * 3 * NPTS;
    float x = p1[n], y = p1[NPTS + n], z = p1[2 * NPTS + n];
    float n1 = x * x + y * y + z * z;

    float d0 = 3.4e38f, d1v = 3.4e38f, d2v = 3.4e38f;
    int   i0 = 0, i1 = 0, i2 = 0;
    for (int s = 0; s < SPTS; s++) {
        float dot = x * sx[s] + y * sy[s] + z * sz[s];
        float d = n1 + sn[s] - 2.0f * dot;            // matches reference form
        if (d < d2v) {
            if (d < d1v) {
                d2v = d1v; i2 = i1;
                if (d < d0) { d1v = d0; i1 = i0; d0 = d; i0 = s; }
                else        { d1v = d;  i1 = s; }
            } else { d2v = d; i2 = s; }
        }
    }
    d0  = fmaxf(d0,  1e-10f);
    d1v = fmaxf(d1v, 1e-10f);
    d2v = fmaxf(d2v, 1e-10f);
    float w0 = 1.0f / d0, w1 = 1.0f / d1v, w2 = 1.0f / d2v;
    float inv = 1.0f / (w0 + w1 + w2);
    int base = (b * NPTS + n) * 3;
    g_idx[base] = i0; g_idx[base + 1] = i1; g_idx[base + 2] = i2;
    g_w[base] = w0 * inv; g_w[base + 1] = w1 * inv; g_w[base + 2] = w2 * inv;
}

// ---------------- tensor-core GEMM (3xTF32), 64x128 tile, K=256 -------------
// MODE 0: Z^T = (W1[:, :256] @ feature2)^T   — staged transpose store
// MODE 2: out = W2 @ relu(bn1(y1)) + b2      — bias + BN partials epilogue
template <int MODE>
__global__ __launch_bounds__(256) void tgemm_kernel(const float* __restrict__ A,
                                                    const float* __restrict__ bias_v,
                                                    const float* __restrict__ Bsrc,
                                                    float* __restrict__ outp) {
    __shared__ float As[16][68];            // [k][m], padded: frag LDS conflict-free
    __shared__ float Bs[16][132];           // [k][n], padded
    __shared__ union {
        float r[2][64][16];                 // MODE2: RS/RQ
        float stage[128][68];               // MODE0: [s][o] transpose staging
    } U;

    const int ASTRIDE = (MODE == 0) ? CIN : HCH;
    const int COLS    = (MODE == 0) ? SPTS : NPTS;

    const int tid = threadIdx.x;
    const int b   = (MODE == 0) ? (blockIdx.x >> 4) : (blockIdx.x >> 6);
    const int n0  = (MODE == 0) ? ((blockIdx.x & 15) << 7)
                                : ((blockIdx.x & 63) << 7);
    const int m0  = blockIdx.y * 64;

    const int am = tid >> 2,  ak = (tid & 3) << 2;    // A-tile load map
    const int bk = tid >> 4,  bn = (tid & 15) << 3;   // B-tile load map
    const int lane = tid & 31, warp = tid >> 5;
    const int wm = warp & 1,  wn = warp >> 1;         // 2x4 warp grid
    const int g = lane >> 2,  tig = lane & 3;

    const float* B_b = (MODE == 2) ? (g_y1 + (long long)b * HCH * NPTS)
                                   : (Bsrc + (long long)b * D2C * SPTS);

    float acc[2][4][4];
    #pragma unroll
    for (int mi = 0; mi < 2; mi++)
        #pragma unroll
        for (int ni = 0; ni < 4; ni++)
            #pragma unroll
            for (int r = 0; r < 4; r++) acc[mi][ni][r] = 0.0f;

    for (int k0 = 0; k0 < 256; k0 += 16) {
        float4 a4 = *(const float4*)(A + (m0 + am) * ASTRIDE + k0 + ak);
        As[ak + 0][am] = a4.x; As[ak + 1][am] = a4.y;
        As[ak + 2][am] = a4.z; As[ak + 3][am] = a4.w;

        const int c = k0 + bk;
        const float* src = B_b + (long long)c * COLS + n0 + bn;
        if (MODE == 2) {
            float sc = g_scale1[c], sh = g_shift1[c];
            float4 v0 = *(const float4*)(src);
            float4 v1 = *(const float4*)(src + 4);
            v0.x = fmaxf(fmaf(v0.x, sc, sh), 0.0f);
            v0.y = fmaxf(fmaf(v0.y, sc, sh), 0.0f);
            v0.z = fmaxf(fmaf(v0.z, sc, sh), 0.0f);
            v0.w = fmaxf(fmaf(v0.w, sc, sh), 0.0f);
            v1.x = fmaxf(fmaf(v1.x, sc, sh), 0.0f);
            v1.y = fmaxf(fmaf(v1.y, sc, sh), 0.0f);
            v1.z = fmaxf(fmaf(v1.z, sc, sh), 0.0f);
            v1.w = fmaxf(fmaf(v1.w, sc, sh), 0.0f);
            *(float4*)&Bs[bk][bn]     = v0;
            *(float4*)&Bs[bk][bn + 4] = v1;
        } else {
            *(float4*)&Bs[bk][bn]     = *(const float4*)(src);
            *(float4*)&Bs[bk][bn + 4] = *(const float4*)(src + 4);
        }
        __syncthreads();

        #pragma unroll
        for (int kk = 0; kk < 16; kk += 8) {
            unsigned ah[2][4], al[2][4];
            #pragma unroll
            for (int mi = 0; mi < 2; mi++) {
                int Am = wm * 32 + mi * 16;
                split_tf32(As[kk + tig][Am + g],         ah[mi][0], al[mi][0]);
                split_tf32(As[kk + tig][Am + 8 + g],     ah[mi][1], al[mi][1]);
                split_tf32(As[kk + 4 + tig][Am + g],     ah[mi][2], al[mi][2]);
                split_tf32(As[kk + 4 + tig][Am + 8 + g], ah[mi][3], al[mi][3]);
            }
            unsigned bh[4][2], bl[4][2];
            #pragma unroll
            for (int ni = 0; ni < 4; ni++) {
                int Bn = wn * 32 + ni * 8 + g;
                split_tf32(Bs[kk + tig][Bn],     bh[ni][0], bl[ni][0]);
                split_tf32(Bs[kk + 4 + tig][Bn], bh[ni][1], bl[ni][1]);
            }
            #pragma unroll
            for (int mi = 0; mi < 2; mi++)
                #pragma unroll
                for (int ni = 0; ni < 4; ni++) {
                    mma8(acc[mi][ni], al[mi], bh[ni]);   // small terms first
                    mma8(acc[mi][ni], ah[mi], bl[ni]);
                    mma8(acc[mi][ni], ah[mi], bh[ni]);
                }
        }
        __syncthreads();
    }

    if (MODE == 0) {
        // stage[s][o] then coalesced float4 store of Z^T[b][s][o]
        #pragma unroll
        for (int mi = 0; mi < 2; mi++) {
            int r0 = wm * 32 + mi * 16 + g;
            int r1 = r0 + 8;
            #pragma unroll
            for (int ni = 0; ni < 4; ni++) {
                int cc = wn * 32 + ni * 8 + 2 * tig;
                U.stage[cc][r0]     = acc[mi][ni][0];
                U.stage[cc + 1][r0] = acc[mi][ni][1];
                U.stage[cc][r1]     = acc[mi][ni][2];
                U.stage[cc + 1][r1] = acc[mi][ni][3];
            }
        }
        __syncthreads();
        float* zt_b = g_zt + b * (SPTS * HCH);
        for (int q = tid; q < 128 * 16; q += 256) {
            int s = q >> 4, o4 = (q & 15) << 2;
            float4 v = *(const float4*)&U.stage[s][o4];
            *(float4*)(zt_b + (n0 + s) * HCH + m0 + o4) = v;
        }
        return;
    }

    // MODE 2 epilogue: bias + store + deterministic BN partials
    float* out_b = outp + b * (HCH * NPTS);
    #pragma unroll
    for (int mi = 0; mi < 2; mi++) {
        #pragma unroll
        for (int h = 0; h < 2; h++) {
            int row = wm * 32 + mi * 16 + g + 8 * h;
            int o = m0 + row;
            float bv = bias_v[o];
            float s = 0.0f, q = 0.0f;
            #pragma unroll
            for (int ni = 0; ni < 4; ni++) {
                float v0 = acc[mi][ni][2 * h + 0] + bv;
                float v1 = acc[mi][ni][2 * h + 1] + bv;
                int n = n0 + wn * 32 + ni * 8 + 2 * tig;
                *(float2*)(out_b + (long long)o * NPTS + n) = make_float2(v0, v1);
                s += v0 + v1;
                q += v0 * v0 + v1 * v1;
            }
            U.r[0][row][wn * 4 + tig] = s;
            U.r[1][row][wn * 4 + tig] = q;
        }
    }
    __syncthreads();
    if (tid < 64) {   // deterministic fixed-order reduction
        float s = 0.0f, q = 0.0f;
        #pragma unroll
        for (int t = 0; t < 16; t++) { s += U.r[0][tid][t]; q += U.r[1][tid][t]; }
        g_psum2[(m0 + tid) * NT + blockIdx.x] = s;
        g_psq2 [(m0 + tid) * NT + blockIdx.x] = q;
    }
}

// ---------------- MODE1 FFMA GEMM: y1 = W1b @ feature1 + gather(Z^T) + b1 ---
__global__ __launch_bounds__(256) void gemm1_kernel(const float* __restrict__ A,
                                                    const float* __restrict__ bias_v,
                                                    const float* __restrict__ Bsrc) {
    __shared__ float As[16][64];
    __shared__ float Bs[16][128];
    __shared__ float RS[64][16];
    __shared__ float RQ[64][16];

    const int tid = threadIdx.x;
    const int b   = blockIdx.x >> 6;
    const int n0  = (blockIdx.x & 63) << 7;
    const int m0  = blockIdx.y * 64;

    const int am = tid >> 2,  ak = (tid & 3) << 2;
    const int bk = tid >> 4,  bn = (tid & 15) << 3;
    const int ty = tid >> 4,  tx = tid & 15;

    const float* B_b = Bsrc + (long long)b * D1C * NPTS;

    float acc[4][8];
    #pragma unroll
    for (int i = 0; i < 4; i++)
        #pragma unroll
        for (int j = 0; j < 8; j++) acc[i][j] = 0.0f;

    for (int k0 = 0; k0 < D1C; k0 += 16) {
        float4 a4 = *(const float4*)(A + (m0 + am) * CIN + k0 + ak);
        As[ak + 0][am] = a4.x; As[ak + 1][am] = a4.y;
        As[ak + 2][am] = a4.z; As[ak + 3][am] = a4.w;

        const int c = k0 + bk;
        const float* src = B_b + (long long)c * NPTS + n0 + bn;
        *(float4*)&Bs[bk][bn]     = *(const float4*)(src);
        *(float4*)&Bs[bk][bn + 4] = *(const float4*)(src + 4);
        __syncthreads();

        #pragma unroll
        for (int k = 0; k < 16; k++) {
            float4 av = *(const float4*)&As[k][ty << 2];
            float4 b0 = *(const float4*)&Bs[k][tx << 3];
            float4 b1 = *(const float4*)&Bs[k][(tx << 3) + 4];
            acc[0][0] = fmaf(av.x, b0.x, acc[0][0]);
            acc[0][1] = fmaf(av.x, b0.y, acc[0][1]);
            acc[0][2] = fmaf(av.x, b0.z, acc[0][2]);
            acc[0][3] = fmaf(av.x, b0.w, acc[0][3]);
            acc[0][4] = fmaf(av.x, b1.x, acc[0][4]);
            acc[0][5] = fmaf(av.x, b1.y, acc[0][5]);
            acc[0][6] = fmaf(av.x, b1.z, acc[0][6]);
            acc[0][7] = fmaf(av.x, b1.w, acc[0][7]);
            acc[1][0] = fmaf(av.y, b0.x, acc[1][0]);
            acc[1][1] = fmaf(av.y, b0.y, acc[1][1]);
            acc[1][2] = fmaf(av.y, b0.z, acc[1][2]);
            acc[1][3] = fmaf(av.y, b0.w, acc[1][3]);
            acc[1][4] = fmaf(av.y, b1.x, acc[1][4]);
            acc[1][5] = fmaf(av.y, b1.y, acc[1][5]);
            acc[1][6] = fmaf(av.y, b1.z, acc[1][6]);
            acc[1][7] = fmaf(av.y, b1.w, acc[1][7]);
            acc[2][0] = fmaf(av.z, b0.x, acc[2][0]);
            acc[2][1] = fmaf(av.z, b0.y, acc[2][1]);
            acc[2][2] = fmaf(av.z, b0.z, acc[2][2]);
            acc[2][3] = fmaf(av.z, b0.w, acc[2][3]);
            acc[2][4] = fmaf(av.z, b1.x, acc[2][4]);
            acc[2][5] = fmaf(av.z, b1.y, acc[2][5]);
            acc[2][6] = fmaf(av.z, b1.z, acc[2][6]);
            acc[2][7] = fmaf(av.z, b1.w, acc[2][7]);
            acc[3][0] = fmaf(av.w, b0.x, acc[3][0]);
            acc[3][1] = fmaf(av.w, b0.y, acc[3][1]);
            acc[3][2] = fmaf(av.w, b0.z, acc[3][2]);
            acc[3][3] = fmaf(av.w, b0.w, acc[3][3]);
            acc[3][4] = fmaf(av.w, b1.x, acc[3][4]);
            acc[3][5] = fmaf(av.w, b1.y, acc[3][5]);
            acc[3][6] = fmaf(av.w, b1.z, acc[3][6]);
            acc[3][7] = fmaf(av.w, b1.w, acc[3][7]);
        }
        __syncthreads();
    }

    // interpolated contribution: sum_j w_j * Z^T[idx_j][o]
    {
        const float* zt_b = g_zt + b * (SPTS * HCH);
        const int o_base = m0 + (ty << 2);
        #pragma unroll
        for (int jj = 0; jj < 8; jj++) {
            int n = n0 + (tx << 3) + jj;
            int base = (b * NPTS + n) * 3;
            int j0i = g_idx[base], j1i = g_idx[base + 1], j2i = g_idx[base + 2];
            float w0 = g_w[base], w1 = g_w[base + 1], w2 = g_w[base + 2];
            float4 z0 = *(const float4*)(zt_b + j0i * HCH + o_base);
            float4 z1 = *(const float4*)(zt_b + j1i * HCH + o_base);
            float4 z2 = *(const float4*)(zt_b + j2i * HCH + o_base);
            acc[0][jj] += w0 * z0.x + w1 * z1.x + w2 * z2.x;
            acc[1][jj] += w0 * z0.y + w1 * z1.y + w2 * z2.y;
            acc[2][jj] += w0 * z0.z + w1 * z1.z + w2 * z2.z;
            acc[3][jj] += w0 * z0.w + w1 * z1.w + w2 * z2.w;
        }
    }

    float* out_b = g_y1 + b * (HCH * NPTS);
    #pragma unroll
    for (int i = 0; i < 4; i++) {
        int o = m0 + (ty << 2) + i;
        float bv = bias_v[o];
        float s = 0.0f, q = 0.0f;
        #pragma unroll
        for (int j = 0; j < 8; j++) {
            acc[i][j] += bv;
            s += acc[i][j];
            q += acc[i][j] * acc[i][j];
        }
        float4 v0 = make_float4(acc[i][0], acc[i][1], acc[i][2], acc[i][3]);
        float4 v1 = make_float4(acc[i][4], acc[i][5], acc[i][6], acc[i][7]);
        *(float4*)(out_b + o * NPTS + n0 + (tx << 3))     = v0;
        *(float4*)(out_b + o * NPTS + n0 + (tx << 3) + 4) = v1;
        RS[(ty << 2) + i][tx] = s;
        RQ[(ty << 2) + i][tx] = q;
    }
    __syncthreads();
    if (tid < 64) {   // deterministic fixed-order reduction
        float s = 0.0f, q = 0.0f;
        #pragma unroll
        for (int t = 0; t < 16; t++) { s += RS[tid][t]; q += RQ[tid][t]; }
        g_psum1[(m0 + tid) * NT + blockIdx.x] = s;
        g_psq1 [(m0 + tid) * NT + blockIdx.x] = q;
    }
}

// ---------------- BN finalize: one block per channel, tree reduction --------
__global__ __launch_bounds__(128) void finalize_kernel(const float* __restrict__ g,
                                                       const float* __restrict__ be,
                                                       int layer) {
    __shared__ float ss[128], sq[128];
    const int o = blockIdx.x;
    const int t = threadIdx.x;
    const float* ps = (layer == 1) ? g_psum1 : g_psum2;
    const float* pq = (layer == 1) ? g_psq1  : g_psq2;
    float s = ps[o * NT + t] + ps[o * NT + t + 128];
    float q = pq[o * NT + t] + pq[o * NT + t + 128];
    ss[t] = s; sq[t] = q;
    __syncthreads();
    #pragma unroll
    for (int off = 64; off > 0; off >>= 1) {
        if (t < off) { ss[t] += ss[t + off]; sq[t] += sq[t + off]; }
        __syncthreads();
    }
    if (t == 0) {
        float mean = ss[0] * (1.0f / BN_TOT);
        float var  = sq[0] * (1.0f / BN_TOT) - mean * mean;
        float rstd = rsqrtf(var + 1e-5f);
        float sc = g[o] * rstd;
        float sh = be[o] - mean * sc;
        if (layer == 1) { g_scale1[o] = sc; g_shift1[o] = sh; }
        else            { g_scale2[o] = sc; g_shift2[o] = sh; }
    }
}

// ---------------- final BN2 + ReLU over d_out -------------------------------
__global__ __launch_bounds__(1024) void bnrelu_kernel(float* __restrict__ out) {
    int e = blockIdx.x * 1024 + threadIdx.x;
    int o = (e >> 13) & (HCH - 1);
    out[e] = fmaxf(fmaf(out[e], g_scale2[o], g_shift2[o]), 0.0f);
}

// ---------------- launch ----------------------------------------------------
extern "C" void kernel_launch(void* const* d_in, const int* in_sizes, int n_in,
                              void* d_out, int out_size) {
    const float* pos1     = (const float*)d_in[0];
    const float* pos2     = (const float*)d_in[1];
    const float* feature1 = (const float*)d_in[2];
    const float* feature2 = (const float*)d_in[3];
    const float* W1 = (const float*)d_in[4];
    const float* b1 = (const float*)d_in[5];
    const float* g1 = (const float*)d_in[6];
    const float* be1 = (const float*)d_in[7];
    const float* W2 = (const float*)d_in[8];
    const float* b2 = (const float*)d_in[9];
    const float* g2 = (const float*)d_in[10];
    const float* be2 = (const float*)d_in[11];
    float* out = (float*)d_out;

    nn_kernel<<<BATCH * 32, 256>>>(pos1, pos2);
    // Z^T = (W1[:, :256] @ feature2)^T  (tensor-core 3xTF32)
    tgemm_kernel<0><<<dim3(BATCH * 16, HCH / 64), 256>>>(W1, b1, feature2, out);
    // y1 = W1[:, 256:] @ feature1 + gather(Z^T) + b1  (FFMA)
    gemm1_kernel<<<dim3(NT, HCH / 64), 256>>>(W1 + D2C, b1, feature1);
    finalize_kernel<<<HCH, 128>>>(g1, be1, 1);
    // out = W2 @ relu(bn1(y1)) + b2  (tensor-core 3xTF32; B read from g_y1)
    tgemm_kernel<2><<<dim3(NT, HCH / 64), 256>>>(W2, b2, feature1, out);
    finalize_kernel<<<HCH, 128>>>(g2, be2, 2);
    bnrelu_kernel<<<(BATCH * HCH * NPTS) / 1024, 1024>>>(out);
}